// round 1
// baseline (speedup 1.0000x reference)
#include <cuda_runtime.h>

#define Bn 64
#define Tn 1024
#define Cn 8
#define NSTEP (2 * Tn - 1)
#define FINF 1000000000.0f
#define ALPHA 0.7f

// softmin constants for gamma = 0.2:
//   exp(-(x-m)/g) = 2^((m-x) * INVGLN2),  INVGLN2 = 1/(g*ln2)
//   smin = m - (g*ln2) * log2(s)
#define INVGLN2 7.2134752044448170f
#define GLN2 0.13862943611198906f

// Deterministic partial sums (written fully every launch)
__device__ float g_mse[Bn * 32];
__device__ float g_r[Bn];

__device__ __forceinline__ float ex2f(float x) {
    float y;
    asm("ex2.approx.ftz.f32 %0, %1;" : "=f"(y) : "f"(x));
    return y;
}
__device__ __forceinline__ float lg2f(float x) {
    float y;
    asm("lg2.approx.ftz.f32 %0, %1;" : "=f"(y) : "f"(x));
    return y;
}

__global__ __launch_bounds__(1024, 1)
void sdtw_kernel(const float* __restrict__ pred, const float* __restrict__ target) {
    // tgtT rows 0..7: -2*target_c[j]; row 8: y2[j]
    __shared__ float tgtT[9][Tn];
    __shared__ float edge[3][32];   // lane-31 R values per warp, rotating k%3

    const int b    = blockIdx.x;
    const int tid  = threadIdx.x;   // DP row i
    const int lane = tid & 31;
    const int warp = tid >> 5;

    // ---- load pred row (registers) + target row (to transposed smem) ----
    const float4* pr = reinterpret_cast<const float4*>(pred + ((size_t)b * Tn + tid) * Cn);
    const float4* tr = reinterpret_cast<const float4*>(target + ((size_t)b * Tn + tid) * Cn);
    float4 p0 = pr[0], p1 = pr[1];
    float4 t0 = tr[0], t1 = tr[1];
    float p[8] = {p0.x, p0.y, p0.z, p0.w, p1.x, p1.y, p1.z, p1.w};
    float t[8] = {t0.x, t0.y, t0.z, t0.w, t1.x, t1.y, t1.z, t1.w};

    float x2 = 0.f, y2 = 0.f, msep = 0.f;
#pragma unroll
    for (int c = 0; c < 8; ++c) {
        x2 = fmaf(p[c], p[c], x2);
        y2 = fmaf(t[c], t[c], y2);
        float d = p[c] - t[c];
        msep = fmaf(d, d, msep);
        tgtT[c][tid] = -2.0f * t[c];
    }
    tgtT[8][tid] = y2;

    // deterministic MSE partial: warp shuffle reduce, fixed slot per warp
#pragma unroll
    for (int off = 16; off > 0; off >>= 1)
        msep += __shfl_xor_sync(0xffffffffu, msep, off);
    if (lane == 0) g_mse[b * 32 + warp] = msep;

    if (tid < 32) { edge[1][tid] = FINF; edge[2][tid] = FINF; }
    __syncthreads();

    // ---- anti-diagonal wavefront ----
    float rp1 = FINF;   // R_{k-1} for this row
    float rp2 = FINF;   // R_{k-2} for this row
    float* e0 = edge[0];   // write (step k)
    float* e1 = edge[2];   // step k-1 edges
    float* e2 = edge[1];   // step k-2 edges

    const int wlo = warp * 32;                 // warp active iff k in [wlo, wlo+31+T-1]
    const int whi = wlo + 31 + (Tn - 1);

#pragma unroll 1
    for (int k = 0; k < NSTEP; ++k) {
        float rnew = FINF;
        if (k >= wlo && k <= whi) {
            const int j = k - tid;
            const bool valid = (j >= 0) && (j < Tn);
            const int jc = valid ? j : 0;

            float up = __shfl_up_sync(0xffffffffu, rp1, 1);
            float dg = __shfl_up_sync(0xffffffffu, rp2, 1);
            if (lane == 0) {
                up = (warp > 0) ? e1[warp - 1] : FINF;
                dg = (warp > 0) ? e2[warp - 1] : ((k == 0) ? 0.0f : FINF);
            }
            const float left = rp1;

            float dot = tgtT[8][jc];
#pragma unroll
            for (int c = 0; c < 8; ++c) dot = fmaf(p[c], tgtT[c][jc], dot);
            const float dval = x2 + dot;

            const float m = fminf(up, fminf(left, dg));
            const float s = ex2f((m - up) * INVGLN2)
                          + ex2f((m - left) * INVGLN2)
                          + ex2f((m - dg) * INVGLN2);
            const float smin = m - GLN2 * lg2f(s);
            rnew = valid ? (dval + smin) : FINF;
        }
        rp2 = rp1;
        rp1 = rnew;
        if (lane == 31) e0[warp] = rnew;
        __syncthreads();
        float* tmp = e2; e2 = e1; e1 = e0; e0 = tmp;
    }

    if (tid == Tn - 1) g_r[b] = rp1;   // R[T-1, T-1]
}

__global__ void finalize_kernel(float* out) {
    __shared__ float sm[256];
    const int t = threadIdx.x;

    float a = 0.f;
    for (int i = t; i < Bn * 32; i += 256) a += g_mse[i];
    sm[t] = a;
    __syncthreads();
#pragma unroll
    for (int s = 128; s > 0; s >>= 1) {
        if (t < s) sm[t] += sm[t + s];
        __syncthreads();
    }
    const float mse_sum = sm[0];
    __syncthreads();

    float r = 0.f;
    for (int i = t; i < Bn; i += 256) r += g_r[i];
    sm[t] = r;
    __syncthreads();
#pragma unroll
    for (int s = 128; s > 0; s >>= 1) {
        if (t < s) sm[t] += sm[t + s];
        __syncthreads();
    }
    if (t == 0) {
        const float mse = mse_sum / (float)(Bn * Tn * Cn);
        const float sdtw = sm[0] / (float)Bn;
        out[0] = ALPHA * mse + (1.0f - ALPHA) * sdtw;
    }
}

extern "C" void kernel_launch(void* const* d_in, const int* in_sizes, int n_in,
                              void* d_out, int out_size) {
    (void)in_sizes; (void)n_in; (void)out_size;
    const float* pred   = (const float*)d_in[0];
    const float* target = (const float*)d_in[1];
    float* out = (float*)d_out;

    sdtw_kernel<<<Bn, 1024>>>(pred, target);
    finalize_kernel<<<1, 256>>>(out);
}

// round 2
// speedup vs baseline: 1.8543x; 1.8543x over previous
#include <cuda_runtime.h>

#define Bn 64
#define Tn 1024
#define NTh 512
#define NIT 1536          // 1535 real iterations padded to multiple of 3
#define FINF 1000000000.0f
#define ALPHA 0.7f
#define GLN2 0.13862943611198906f      // gamma*ln2
#define SSCALE 2.6857913f              // sqrt(1/(gamma*ln2))

__device__ float g_mse[Bn * 16];
__device__ float g_r[Bn];

__device__ __forceinline__ float ex2f(float x) {
    float y; asm("ex2.approx.ftz.f32 %0, %1;" : "=f"(y) : "f"(x)); return y;
}
__device__ __forceinline__ float lg2f(float x) {
    float y; asm("lg2.approx.ftz.f32 %0, %1;" : "=f"(y) : "f"(x)); return y;
}

// Scaled-domain recursion: R' = INVGLN2 * R.
// softmin' = v0 - log2(1 + 2^(v0-mid) + 2^(v0-max)),  v0 = min3.
// D' computed from SSCALE-scaled pred/target, so no multiplies in the loop.

__global__ __launch_bounds__(NTh, 1)
void sdtw_kernel(const float* __restrict__ pred, const float* __restrict__ target)
{
    __shared__ float4 tgA[Tn];      // -2*SSCALE*target[c=0..3]
    __shared__ float4 tgB[Tn];      // -2*SSCALE*target[c=4..7]
    __shared__ float  y2s[Tn];      // SSCALE^2 * sum(target^2)
    __shared__ float  edge[3][16];  // lane-31 row1 values per warp, slot = m%3

    const int b    = blockIdx.x;
    const int t    = threadIdx.x;   // owns rows 2t, 2t+1
    const int lane = t & 31;
    const int warp = t >> 5;

    const float* prow = pred   + ((size_t)b * Tn + 2 * (size_t)t) * 8;
    const float* trow = target + ((size_t)b * Tn + 2 * (size_t)t) * 8;

    float P0[8], P1[8], ta[8], tb[8];
    float x20 = 0.f, x21 = 0.f, y20 = 0.f, y21 = 0.f, msep = 0.f;
#pragma unroll
    for (int c = 0; c < 8; ++c) {
        float p0 = prow[c], p1 = prow[8 + c];
        float u0 = trow[c], u1 = trow[8 + c];
        float d0 = p0 - u0, d1 = p1 - u1;
        msep = fmaf(d0, d0, msep); msep = fmaf(d1, d1, msep);
        float ps0 = p0 * SSCALE, ps1 = p1 * SSCALE;
        float ts0 = u0 * SSCALE, ts1 = u1 * SSCALE;
        P0[c] = ps0; P1[c] = ps1;
        x20 = fmaf(ps0, ps0, x20); x21 = fmaf(ps1, ps1, x21);
        y20 = fmaf(ts0, ts0, y20); y21 = fmaf(ts1, ts1, y21);
        ta[c] = -2.f * ts0; tb[c] = -2.f * ts1;
    }
    tgA[2 * t]     = make_float4(ta[0], ta[1], ta[2], ta[3]);
    tgB[2 * t]     = make_float4(ta[4], ta[5], ta[6], ta[7]);
    tgA[2 * t + 1] = make_float4(tb[0], tb[1], tb[2], tb[3]);
    tgB[2 * t + 1] = make_float4(tb[4], tb[5], tb[6], tb[7]);
    y2s[2 * t]     = y20;
    y2s[2 * t + 1] = y21;

    // deterministic MSE partial (fixed slot per warp)
#pragma unroll
    for (int off = 16; off > 0; off >>= 1)
        msep += __shfl_xor_sync(0xffffffffu, msep, off);
    if (lane == 0) g_mse[b * 16 + warp] = msep;

    if (t < 48) ((float*)edge)[t] = FINF;
    __syncthreads();

    float r0 = FINF, r1 = FINF, nbrA = FINF, nbrB = FINF;
    const int wlo = warp * 32;
    const int whi = wlo + 31 + (Tn - 1);

// One wavefront iteration at global step M; writes edge slot SW=M%3,
// reads neighbor slot SR1=(M-1)%3. nbrB (M-2 value) comes from rotation.
#define DTW_STEP(M, SW, SR1)                                                   \
  {                                                                            \
    if ((M) >= wlo && (M) <= whi) {                                            \
      float sh = __shfl_up_sync(0xffffffffu, r1, 1);                           \
      nbrB = nbrA; nbrA = sh;                                                  \
      if (lane == 0) {                                                         \
        nbrA = (warp > 0) ? edge[SR1][warp - 1] : FINF;                        \
        if (warp == 0) nbrB = ((M) == 0) ? 0.0f : FINF;                        \
      }                                                                        \
      int j = (M) - t;                                                         \
      int jc = j < 0 ? 0 : (j > Tn - 1 ? Tn - 1 : j);                          \
      float4 ga = tgA[jc]; float4 gb = tgB[jc]; float y2j = y2s[jc];           \
      float D0 = x20 + y2j, D1 = x21 + y2j;                                    \
      D0 = fmaf(P0[0], ga.x, D0); D0 = fmaf(P0[1], ga.y, D0);                  \
      D0 = fmaf(P0[2], ga.z, D0); D0 = fmaf(P0[3], ga.w, D0);                  \
      D0 = fmaf(P0[4], gb.x, D0); D0 = fmaf(P0[5], gb.y, D0);                  \
      D0 = fmaf(P0[6], gb.z, D0); D0 = fmaf(P0[7], gb.w, D0);                  \
      D1 = fmaf(P1[0], ga.x, D1); D1 = fmaf(P1[1], ga.y, D1);                  \
      D1 = fmaf(P1[2], ga.z, D1); D1 = fmaf(P1[3], ga.w, D1);                  \
      D1 = fmaf(P1[4], gb.x, D1); D1 = fmaf(P1[5], gb.y, D1);                  \
      D1 = fmaf(P1[6], gb.z, D1); D1 = fmaf(P1[7], gb.w, D1);                  \
      bool valid = ((unsigned)j < (unsigned)Tn);                               \
      /* cell (2t, j): up=nbrA, left=r0, diag=nbrB */                          \
      float mn  = fminf(nbrA, r0), mx  = fmaxf(nbrA, r0);                      \
      float v0  = fminf(mn, nbrB), md  = fmaxf(mn, nbrB);                      \
      float s0  = 1.0f + ex2f(v0 - md) + ex2f(v0 - mx);                        \
      float r0n = (D0 + v0) - lg2f(s0);                                        \
      r0n = valid ? r0n : FINF;                                                \
      /* cell (2t+1, j): up=r0n, left=r1, diag=r0(prev) */                     \
      float mn1 = fminf(r0n, r1), mx1 = fmaxf(r0n, r1);                        \
      float v1  = fminf(mn1, r0), md1 = fmaxf(mn1, r0);                        \
      float s1  = 1.0f + ex2f(v1 - md1) + ex2f(v1 - mx1);                      \
      float r1n = (D1 + v1) - lg2f(s1);                                        \
      r1n = valid ? r1n : FINF;                                                \
      r0 = r0n; r1 = r1n;                                                      \
      if (lane == 31) edge[SW][warp] = r1n;                                    \
    }                                                                          \
    __syncthreads();                                                           \
  }

    int m = 0;
#pragma unroll 1
    for (int it = 0; it < NIT / 3; ++it) {
        DTW_STEP(m,     0, 2)
        DTW_STEP(m + 1, 1, 0)
        DTW_STEP(m + 2, 2, 1)
        m += 3;
    }
#undef DTW_STEP

    if (t == NTh - 1) g_r[b] = r1;   // R'[T-1][T-1]
}

__global__ void finalize_kernel(float* out)
{
    __shared__ float sm[256];
    const int t = threadIdx.x;

    float a = 0.f;
    for (int i = t; i < Bn * 16; i += 256) a += g_mse[i];
    sm[t] = a;
    __syncthreads();
#pragma unroll
    for (int s = 128; s > 0; s >>= 1) {
        if (t < s) sm[t] += sm[t + s];
        __syncthreads();
    }
    const float mse_sum = sm[0];
    __syncthreads();

    float r = 0.f;
    for (int i = t; i < Bn; i += 256) r += g_r[i];
    sm[t] = r;
    __syncthreads();
#pragma unroll
    for (int s = 128; s > 0; s >>= 1) {
        if (t < s) sm[t] += sm[t + s];
        __syncthreads();
    }
    if (t == 0) {
        const float mse  = mse_sum / (float)(Bn * Tn * 8);
        const float sdtw = (GLN2 * sm[0]) / (float)Bn;   // un-scale
        out[0] = ALPHA * mse + (1.0f - ALPHA) * sdtw;
    }
}

extern "C" void kernel_launch(void* const* d_in, const int* in_sizes, int n_in,
                              void* d_out, int out_size)
{
    (void)in_sizes; (void)n_in; (void)out_size;
    const float* pred   = (const float*)d_in[0];
    const float* target = (const float*)d_in[1];
    float* out = (float*)d_out;

    sdtw_kernel<<<Bn, NTh>>>(pred, target);
    finalize_kernel<<<1, 256>>>(out);
}

// round 3
// speedup vs baseline: 2.5336x; 1.3664x over previous
#include <cuda_runtime.h>
#include <cstdint>

#define Bn 64
#define Tn 1024
#define NTh 512
#define NWARP 16
#define NLOC (Tn + 31)          // 1055 local iterations per warp
#define FINF 1000000000.0f
#define ALPHA 0.7f
#define GLN2 0.13862943611198906f      // gamma*ln2
#define SSCALE 2.6857913f              // sqrt(1/(gamma*ln2))

__device__ float g_mse[Bn * NWARP];
__device__ float g_r[Bn];

__device__ __forceinline__ float ex2f(float x) {
    float y; asm("ex2.approx.ftz.f32 %0, %1;" : "=f"(y) : "f"(x)); return y;
}
__device__ __forceinline__ float lg2f(float x) {
    float y; asm("lg2.approx.ftz.f32 %0, %1;" : "=f"(y) : "f"(x)); return y;
}
__device__ __forceinline__ int ld_acq(const int* p) {
    int v; uint32_t a = (uint32_t)__cvta_generic_to_shared(p);
    asm volatile("ld.acquire.cta.shared.b32 %0, [%1];" : "=r"(v) : "r"(a));
    return v;
}
__device__ __forceinline__ void st_rel(int* p, int v) {
    uint32_t a = (uint32_t)__cvta_generic_to_shared(p);
    asm volatile("st.release.cta.shared.b32 [%0], %1;" :: "r"(a), "r"(v));
}

__global__ __launch_bounds__(NTh, 1)
void sdtw_kernel(const float* __restrict__ pred, const float* __restrict__ target)
{
    __shared__ float4 tgA[Tn];          // -2*SSCALE*target[0..3]
    __shared__ float4 tgB[Tn];          // -2*SSCALE*target[4..7]
    __shared__ float  y2s[Tn];          // SSCALE^2 * |target|^2
    __shared__ float  edge[NWARP][64];  // lane31 r1 history ring per warp
    __shared__ int    prog[NWARP];      // completed local iters per warp

    const int b    = blockIdx.x;
    const int t    = threadIdx.x;
    const int lane = t & 31;
    const int w    = t >> 5;

    // ---- preprocessing: rows 2t, 2t+1 ----
    const float* prow = pred   + ((size_t)b * Tn + 2 * (size_t)t) * 8;
    const float* trow = target + ((size_t)b * Tn + 2 * (size_t)t) * 8;

    float P0[8], P1[8], ta[8], tb[8];
    float x20 = 0.f, x21 = 0.f, y20 = 0.f, y21 = 0.f, msep = 0.f;
#pragma unroll
    for (int c = 0; c < 8; ++c) {
        float p0 = prow[c], p1 = prow[8 + c];
        float u0 = trow[c], u1 = trow[8 + c];
        float d0 = p0 - u0, d1 = p1 - u1;
        msep = fmaf(d0, d0, msep); msep = fmaf(d1, d1, msep);
        float ps0 = p0 * SSCALE, ps1 = p1 * SSCALE;
        float ts0 = u0 * SSCALE, ts1 = u1 * SSCALE;
        P0[c] = ps0; P1[c] = ps1;
        x20 = fmaf(ps0, ps0, x20); x21 = fmaf(ps1, ps1, x21);
        y20 = fmaf(ts0, ts0, y20); y21 = fmaf(ts1, ts1, y21);
        ta[c] = -2.f * ts0; tb[c] = -2.f * ts1;
    }
    tgA[2 * t]     = make_float4(ta[0], ta[1], ta[2], ta[3]);
    tgB[2 * t]     = make_float4(ta[4], ta[5], ta[6], ta[7]);
    tgA[2 * t + 1] = make_float4(tb[0], tb[1], tb[2], tb[3]);
    tgB[2 * t + 1] = make_float4(tb[4], tb[5], tb[6], tb[7]);
    y2s[2 * t]     = y20;
    y2s[2 * t + 1] = y21;

#pragma unroll
    for (int off = 16; off > 0; off >>= 1)
        msep += __shfl_xor_sync(0xffffffffu, msep, off);
    if (lane == 0) g_mse[b * NWARP + w] = msep;

    if (t < NWARP) prog[t] = 0;
    __syncthreads();   // the ONLY block barrier

    // ---- warp-systolic wavefront ----
    // Warp w owns rows [64w, 64w+64); lane l rows 64w+2l, 64w+2l+1.
    // Local iter n: lane l works column j = n - l.
    // Lane 0's up/diag come from warp w-1's edge ring (its iter n+31 / n+30).
    float r0 = FINF, r1 = FINF;
    float nbrA = (w == 0 && lane == 0) ? 0.0f : FINF;   // warp0 diag seed for (0,0)
    float nbrB = FINF;

    const float* edgeP = (w > 0) ? edge[w - 1] : edge[0];
    float*       edgeW = edge[w];
    const bool hasProd = (w > 0);
    const bool hasCons = (w < NWARP - 1);

#define DTW_ITER(N)                                                            \
  {                                                                            \
    float sh = __shfl_up_sync(0xffffffffu, r1, 1);                             \
    float newA;                                                                \
    if (lane == 0)                                                             \
      newA = hasProd ? edgeP[((N) + 31) & 63] : FINF;                          \
    else                                                                       \
      newA = sh;                                                               \
    nbrB = nbrA; nbrA = newA;                                                  \
    int j = (N) - lane;                                                        \
    bool valid = ((unsigned)j < (unsigned)Tn);                                 \
    int jc = valid ? j : 0;                                                    \
    float4 ga = tgA[jc]; float4 gb = tgB[jc]; float y2j = y2s[jc];             \
    float D0 = x20 + y2j, D1 = x21 + y2j;                                      \
    D0 = fmaf(P0[0], ga.x, D0); D0 = fmaf(P0[1], ga.y, D0);                    \
    D0 = fmaf(P0[2], ga.z, D0); D0 = fmaf(P0[3], ga.w, D0);                    \
    D0 = fmaf(P0[4], gb.x, D0); D0 = fmaf(P0[5], gb.y, D0);                    \
    D0 = fmaf(P0[6], gb.z, D0); D0 = fmaf(P0[7], gb.w, D0);                    \
    D1 = fmaf(P1[0], ga.x, D1); D1 = fmaf(P1[1], ga.y, D1);                    \
    D1 = fmaf(P1[2], ga.z, D1); D1 = fmaf(P1[3], ga.w, D1);                    \
    D1 = fmaf(P1[4], gb.x, D1); D1 = fmaf(P1[5], gb.y, D1);                    \
    D1 = fmaf(P1[6], gb.z, D1); D1 = fmaf(P1[7], gb.w, D1);                    \
    float mn  = fminf(nbrA, r0), mx  = fmaxf(nbrA, r0);                        \
    float v0  = fminf(mn, nbrB), md  = fmaxf(mn, nbrB);                        \
    float s0  = 1.0f + ex2f(v0 - md) + ex2f(v0 - mx);                          \
    float r0n = (D0 + v0) - lg2f(s0);                                          \
    r0n = valid ? r0n : FINF;                                                  \
    float mn1 = fminf(r0n, r1), mx1 = fmaxf(r0n, r1);                          \
    float v1  = fminf(mn1, r1 > r0n ? r0 : r0), md1 = fmaxf(mn1, r0);          \
    v1 = fminf(mn1, r0);                                                       \
    float s1  = 1.0f + ex2f(v1 - md1) + ex2f(v1 - mx1);                        \
    float r1n = (D1 + v1) - lg2f(s1);                                          \
    r1n = valid ? r1n : FINF;                                                  \
    r0 = r0n; r1 = r1n;                                                        \
    if (lane == 31) edgeW[(N) & 63] = r1n;                                     \
  }

    int n = 0;
#pragma unroll 1
    for (int mb = 0; mb < 131; ++mb) {     // 131*8 = 1048 iters
        if (hasProd) {
            int need = ((n + 7 < 1023) ? (n + 7) : 1023) + 32;
            while (ld_acq(&prog[w - 1]) < need) __nanosleep(32);
        }
        if (hasCons && n >= 87) {
            int lim = n - 86;
            while (ld_acq(&prog[w + 1]) < lim) __nanosleep(32);
        }
        DTW_ITER(n)     DTW_ITER(n + 1) DTW_ITER(n + 2) DTW_ITER(n + 3)
        DTW_ITER(n + 4) DTW_ITER(n + 5) DTW_ITER(n + 6) DTW_ITER(n + 7)
        n += 8;
        st_rel(&prog[w], n);
    }
    // tail: n = 1048..1054 (7 iters)
    {
        if (hasProd) {
            int need = 1055;
            while (ld_acq(&prog[w - 1]) < need) __nanosleep(32);
        }
        DTW_ITER(n)     DTW_ITER(n + 1) DTW_ITER(n + 2) DTW_ITER(n + 3)
        DTW_ITER(n + 4) DTW_ITER(n + 5) DTW_ITER(n + 6)
        st_rel(&prog[w], NLOC);
    }
#undef DTW_ITER

    if (w == NWARP - 1 && lane == 31) g_r[b] = r1;   // R'[T-1][T-1]
}

__global__ void finalize_kernel(float* out)
{
    __shared__ float sm[256];
    const int t = threadIdx.x;

    float a = 0.f;
    for (int i = t; i < Bn * NWARP; i += 256) a += g_mse[i];
    sm[t] = a;
    __syncthreads();
#pragma unroll
    for (int s = 128; s > 0; s >>= 1) {
        if (t < s) sm[t] += sm[t + s];
        __syncthreads();
    }
    const float mse_sum = sm[0];
    __syncthreads();

    float r = 0.f;
    for (int i = t; i < Bn; i += 256) r += g_r[i];
    sm[t] = r;
    __syncthreads();
#pragma unroll
    for (int s = 128; s > 0; s >>= 1) {
        if (t < s) sm[t] += sm[t + s];
        __syncthreads();
    }
    if (t == 0) {
        const float mse  = mse_sum / (float)(Bn * Tn * 8);
        const float sdtw = (GLN2 * sm[0]) / (float)Bn;
        out[0] = ALPHA * mse + (1.0f - ALPHA) * sdtw;
    }
}

extern "C" void kernel_launch(void* const* d_in, const int* in_sizes, int n_in,
                              void* d_out, int out_size)
{
    (void)in_sizes; (void)n_in; (void)out_size;
    const float* pred   = (const float*)d_in[0];
    const float* target = (const float*)d_in[1];
    float* out = (float*)d_out;

    sdtw_kernel<<<Bn, NTh>>>(pred, target);
    finalize_kernel<<<1, 256>>>(out);
}